// round 1
// baseline (speedup 1.0000x reference)
#include <cuda_runtime.h>
#include <cuda_bf16.h>

// Fused MoE router gate:
//   logits = (H[T,D] @ W[E,D]^T) * cal_scale + cal_bias   (fp32)
//   probs  = softmax(logits)  -> out[0 : T*E]
//   topk-8 weights            -> out[T*E : T*E + T*8]
//   topk-8 indices (as float) -> out[T*E + T*8 : T*E + T*16]
//
// T=16384, D=2048, E=64 for this problem (derived at launch from in_sizes).

#define KC  16      // K chunk per stage
#define MT  64      // token tile per block
#define NE  64      // experts (== E, hardcoded in phase 2)
#define TPB 256

__global__ __launch_bounds__(TPB, 2)
void router_fused(const float* __restrict__ H,
                  const float* __restrict__ W,
                  const float* __restrict__ cal_scale,
                  const float* __restrict__ cal_bias,
                  float* __restrict__ out_probs,
                  float* __restrict__ out_w,
                  float* __restrict__ out_idx,
                  int T, int D)
{
    // Transposed tiles [k][m] so compute-side loads are LDS.128 along m/n.
    __shared__ __align__(16) float As[2][KC][MT + 4];
    __shared__ __align__(16) float Bs[2][KC][NE + 4];
    __shared__ float Lg[MT][NE + 1];

    const int tid = threadIdx.x;
    const int tx  = tid & 15;          // expert group: n0 = tx*4
    const int ty  = tid >> 4;          // token group:  m0 = ty*4
    const int m_base = blockIdx.x * MT;

    // Loader mapping: each thread loads one float4 of A and one of B per stage.
    const int lrow = tid >> 2;         // 0..63 (token row for A, expert row for B)
    const int lk   = (tid & 3) << 2;   // 0,4,8,12 (k offset within chunk)

    const bool a_ok = (m_base + lrow) < T;
    const float* Ap = H + (size_t)(m_base + lrow) * D + lk;
    const float* Bp = W + (size_t)lrow * D + lk;

    const float4 z4 = make_float4(0.f, 0.f, 0.f, 0.f);
    float4 a_pf = a_ok ? *(const float4*)Ap : z4;
    float4 b_pf = *(const float4*)Bp;

    float acc[4][4];
    #pragma unroll
    for (int i = 0; i < 4; ++i)
        #pragma unroll
        for (int j = 0; j < 4; ++j) acc[i][j] = 0.f;

    const int KT = D / KC;             // 128 stages
    int buf = 0;
    for (int kt = 0; kt < KT; ++kt) {
        // Store current prefetch into smem (transposed).
        As[buf][lk + 0][lrow] = a_pf.x;
        As[buf][lk + 1][lrow] = a_pf.y;
        As[buf][lk + 2][lrow] = a_pf.z;
        As[buf][lk + 3][lrow] = a_pf.w;
        Bs[buf][lk + 0][lrow] = b_pf.x;
        Bs[buf][lk + 1][lrow] = b_pf.y;
        Bs[buf][lk + 2][lrow] = b_pf.z;
        Bs[buf][lk + 3][lrow] = b_pf.w;
        __syncthreads();

        // Prefetch next stage from GMEM (hides DRAM/L2 latency under compute).
        if (kt + 1 < KT) {
            const float* Apn = Ap + (size_t)(kt + 1) * KC;
            const float* Bpn = Bp + (size_t)(kt + 1) * KC;
            a_pf = a_ok ? *(const float4*)Apn : z4;
            b_pf = *(const float4*)Bpn;
        }

        // Rank-1 updates over this K chunk.
        #pragma unroll
        for (int k = 0; k < KC; ++k) {
            float4 av = *(const float4*)&As[buf][k][ty << 2];
            float4 bv = *(const float4*)&Bs[buf][k][tx << 2];
            const float a0 = av.x, a1 = av.y, a2 = av.z, a3 = av.w;
            const float b0 = bv.x, b1 = bv.y, b2 = bv.z, b3 = bv.w;
            acc[0][0] += a0 * b0; acc[0][1] += a0 * b1; acc[0][2] += a0 * b2; acc[0][3] += a0 * b3;
            acc[1][0] += a1 * b0; acc[1][1] += a1 * b1; acc[1][2] += a1 * b2; acc[1][3] += a1 * b3;
            acc[2][0] += a2 * b0; acc[2][1] += a2 * b1; acc[2][2] += a2 * b2; acc[2][3] += a2 * b3;
            acc[3][0] += a3 * b0; acc[3][1] += a3 * b1; acc[3][2] += a3 * b2; acc[3][3] += a3 * b3;
        }
        buf ^= 1;
    }

    // Calibrate and stage logits in shared memory.
    #pragma unroll
    for (int j = 0; j < 4; ++j) {
        const int n = (tx << 2) + j;
        const float s = cal_scale[n];
        const float b = cal_bias[n];
        #pragma unroll
        for (int i = 0; i < 4; ++i)
            Lg[(ty << 2) + i][n] = acc[i][j] * s + b;
    }
    __syncthreads();

    // Phase 2: warp-per-token softmax + top-8 (E = 64 -> 2 values per lane).
    const int warp = tid >> 5;
    const int lane = tid & 31;
    for (int t = warp; t < MT; t += (TPB / 32)) {
        const int tg = m_base + t;
        if (tg >= T) break;

        float v0 = Lg[t][lane];
        float v1 = Lg[t][lane + 32];

        float mx = fmaxf(v0, v1);
        #pragma unroll
        for (int o = 16; o; o >>= 1)
            mx = fmaxf(mx, __shfl_xor_sync(0xffffffffu, mx, o));

        float e0 = expf(v0 - mx);
        float e1 = expf(v1 - mx);
        float s = e0 + e1;
        #pragma unroll
        for (int o = 16; o; o >>= 1)
            s += __shfl_xor_sync(0xffffffffu, s, o);

        const float inv = 1.0f / s;
        float p0 = e0 * inv;
        float p1 = e1 * inv;

        out_probs[(size_t)tg * NE + lane]      = p0;
        out_probs[(size_t)tg * NE + lane + 32] = p1;

        // 8 rounds of warp argmax; ties -> lower index (matches jax.lax.top_k).
        #pragma unroll
        for (int r = 0; r < 8; ++r) {
            float bv; int bi;
            if (p0 >= p1) { bv = p0; bi = lane; }
            else          { bv = p1; bi = lane + 32; }
            #pragma unroll
            for (int o = 16; o; o >>= 1) {
                const float ov = __shfl_xor_sync(0xffffffffu, bv, o);
                const int   oi = __shfl_xor_sync(0xffffffffu, bi, o);
                if (ov > bv || (ov == bv && oi < bi)) { bv = ov; bi = oi; }
            }
            if (lane == 0) {
                out_w[(size_t)tg * 8 + r]   = bv;
                out_idx[(size_t)tg * 8 + r] = (float)bi;
            }
            if (bi == lane)           p0 = -1.0f;
            else if (bi == lane + 32) p1 = -1.0f;
        }
    }
}

extern "C" void kernel_launch(void* const* d_in, const int* in_sizes, int n_in,
                              void* d_out, int out_size)
{
    const float* H  = (const float*)d_in[0];   // hidden_states [B,S,D] fp32
    const float* W  = (const float*)d_in[1];   // router_weight [E,D]  fp32
    const float* cs = (const float*)d_in[2];   // cal_scale [E]
    const float* cb = (const float*)d_in[3];   // cal_bias  [E]

    const int E = in_sizes[2];                 // 64
    const int D = in_sizes[1] / E;             // 2048
    const int T = in_sizes[0] / D;             // 16384

    float* out       = (float*)d_out;
    float* out_probs = out;                                // [T, E]
    float* out_w     = out + (size_t)T * E;                // [T, 8]
    float* out_idx   = out_w + (size_t)T * 8;              // [T, 8] (indices as float)

    const int grid = (T + MT - 1) / MT;
    router_fused<<<grid, TPB>>>(H, W, cs, cb, out_probs, out_w, out_idx, T, D);
}